// round 6
// baseline (speedup 1.0000x reference)
#include <cuda_runtime.h>

// SPADE: InstanceNorm2d(affine=False) + per-pixel class-conditional affine.
// x[8,128,256,256] f32, segmap[8,20,256,256] f32, weight/bias[20,128] f32.
//
// R6: persistent kernel, 512 co-resident blocks. Every phase gives EVERY
// block an identical item mix (no role split -> no quantization imbalance):
//   phase 0:   argmax(b) ; stats(0, b)
//   phase k:   apply(k-1, b) ; stats(k, b) ; apply(k-1, b+512)
//   tail:      apply(7, b) ; apply(7, b+512)
// stats fills L2 with x_k while apply drains x_{k-1} from L2 (evict-first
// reads, streaming writes). 8 grid barriers, monotonic-generation counter
// (CUDA-graph-replay safe, no host-side state).

#define N_   8
#define C_   128
#define H_   256
#define W_   256
#define L_   20
#define HW_  (H_ * W_)      // 65536
#define EPS_ 1e-5f

#define GRID    512
#define THREADS 256
#define CGRP    8            // channels per apply item (16 cgroups)
#define WB_STRIDE 129        // padded stride (<=2-way LDS bank conflicts)

// Quarter-plane partials (sum, sumsq), double-buffered by image parity.
__device__ float2 g_part[2][C_ * 4];
// Per-pixel argmax class id.
__device__ unsigned char g_cls[N_ * HW_];   // 512 KB
// Grid barrier: g_gen monotonic across launches/replays.
__device__ unsigned int g_count = 0;
__device__ unsigned int g_gen   = 0;

// ---------------------------------------------------------------------------
__device__ __forceinline__ void grid_barrier() {
    __syncthreads();
    if (threadIdx.x == 0) {
        unsigned int snap = *(volatile unsigned int*)&g_gen;
        __threadfence();
        unsigned int t = atomicAdd(&g_count, 1u);
        if (t == GRID - 1) {
            atomicExch(&g_count, 0u);
            __threadfence();
            atomicAdd(&g_gen, 1u);
        } else {
            while (*(volatile unsigned int*)&g_gen == snap) { __nanosleep(64); }
        }
        __threadfence();
    }
    __syncthreads();
}

// ---------------------------------------------------------------------------
// Stats item s in [0,512): plane c = s>>2, quarter q = s&3 (16384 floats).
// Normal cached loads -> x_n resident in L2 for next phase's apply.
// ---------------------------------------------------------------------------
__device__ __forceinline__ void do_stats_item(const float* __restrict__ x, int n, int s) {
    const int c = s >> 2;
    const int q = s & 3;
    const float4* __restrict__ p =
        reinterpret_cast<const float4*>(x + (size_t)(n * C_ + c) * HW_) + q * 4096;

    float sm = 0.f, s2 = 0.f;
    #pragma unroll
    for (int i = 0; i < 16; i++) {             // 16 * 256 = 4096 float4
        float4 v = __ldg(p + i * 256 + threadIdx.x);
        sm += (v.x + v.y) + (v.z + v.w);
        s2 += v.x * v.x + v.y * v.y + v.z * v.z + v.w * v.w;
    }
    #pragma unroll
    for (int o = 16; o > 0; o >>= 1) {
        sm += __shfl_down_sync(0xFFFFFFFFu, sm, o);
        s2 += __shfl_down_sync(0xFFFFFFFFu, s2, o);
    }
    __shared__ float ss[8], ss2[8];
    const int wid = threadIdx.x >> 5, lid = threadIdx.x & 31;
    if (lid == 0) { ss[wid] = sm; ss2[wid] = s2; }
    __syncthreads();
    if (threadIdx.x == 0) {
        float ts = 0.f, ts2 = 0.f;
        #pragma unroll
        for (int i = 0; i < 8; i++) { ts += ss[i]; ts2 += ss2[i]; }
        g_part[n & 1][c * 4 + q] = make_float2(ts, ts2);
    }
    __syncthreads();
}

// ---------------------------------------------------------------------------
// Argmax item i in [0,512): 1024 consecutive pixels (thread = float4).
// Streaming loads so segmap doesn't evict x_0.
// ---------------------------------------------------------------------------
__device__ __forceinline__ void do_argmax_item(const float* __restrict__ seg, int i) {
    const int idx = i * THREADS + threadIdx.x;           // 0 .. 131071
    const int n   = idx >> 14;                           // / (HW/4)
    const int p4  = idx & 16383;
    const float4* __restrict__ s =
        reinterpret_cast<const float4*>(seg + (size_t)n * L_ * HW_) + p4;

    float4 best = __ldcs(s);
    int b0 = 0, b1 = 0, b2 = 0, b3 = 0;
    #pragma unroll
    for (int l = 1; l < L_; l++) {
        float4 v = __ldcs(s + (size_t)l * (HW_ / 4));
        if (v.x > best.x) { best.x = v.x; b0 = l; }
        if (v.y > best.y) { best.y = v.y; b1 = l; }
        if (v.z > best.z) { best.z = v.z; b2 = l; }
        if (v.w > best.w) { best.w = v.w; b3 = l; }
    }
    *reinterpret_cast<uchar4*>(g_cls + (size_t)n * HW_ + p4 * 4) =
        make_uchar4((unsigned char)b0, (unsigned char)b1,
                    (unsigned char)b2, (unsigned char)b3);
}

// ---------------------------------------------------------------------------
// Apply item a in [0,1024): cgroup = a&15 (8 channels), slab = a>>4 (4 rows).
// x reads: __ldcs (last use, L2 hit from this image's stats phase).
// out writes: __stcs (streaming).
// ---------------------------------------------------------------------------
__device__ __forceinline__ void do_apply_item(
    const float* __restrict__ x, float* __restrict__ out,
    const float2* __restrict__ s_wb, const float2* __restrict__ s_ms,
    int n, int a)
{
    const int c0  = (a & 15) * CGRP;
    const int h0  = (a >> 4) << 2;
    const int tid = threadIdx.x;

    const int r    = tid >> 6;
    const int col4 = (tid & 63) << 2;
    const int pix  = (h0 + r) * W_ + col4;

    const uchar4 cl = *reinterpret_cast<const uchar4*>(g_cls + (size_t)n * HW_ + pix);
    const int i0 = cl.x * WB_STRIDE + c0, i1 = cl.y * WB_STRIDE + c0,
              i2 = cl.z * WB_STRIDE + c0, i3 = cl.w * WB_STRIDE + c0;

    const float* __restrict__ xn = x   + (size_t)(n * C_ + c0) * HW_ + pix;
    float*       __restrict__ on = out + (size_t)(n * C_ + c0) * HW_ + pix;

    float4 v[CGRP];
    #pragma unroll
    for (int c = 0; c < CGRP; c++)             // 8 outstanding 16B loads
        v[c] = __ldcs(reinterpret_cast<const float4*>(xn + (size_t)c * HW_));
    #pragma unroll
    for (int c = 0; c < CGRP; c++) {
        const float2 ms = s_ms[c0 + c];
        const float2 w0 = s_wb[i0 + c];
        const float2 w1 = s_wb[i1 + c];
        const float2 w2 = s_wb[i2 + c];
        const float2 w3 = s_wb[i3 + c];
        float4 o;
        o.x = fmaf((v[c].x - ms.x) * ms.y, w0.x, w0.y);
        o.y = fmaf((v[c].y - ms.x) * ms.y, w1.x, w1.y);
        o.z = fmaf((v[c].z - ms.x) * ms.y, w2.x, w2.y);
        o.w = fmaf((v[c].w - ms.x) * ms.y, w3.x, w3.y);
        __stcs(reinterpret_cast<float4*>(on + (size_t)c * HW_), o);
    }
}

// ---------------------------------------------------------------------------
// Finalize per-channel (mean, invstd) for image n into smem.
// ---------------------------------------------------------------------------
__device__ __forceinline__ void finalize_stats(float2* s_ms, int n) {
    if (threadIdx.x < C_) {
        const float2* pp = &g_part[n & 1][threadIdx.x * 4];
        float ts  = (pp[0].x + pp[1].x) + (pp[2].x + pp[3].x);
        float ts2 = (pp[0].y + pp[1].y) + (pp[2].y + pp[3].y);
        const float inv_hw = 1.0f / (float)HW_;
        float mean = ts * inv_hw;
        float var  = ts2 * inv_hw - mean * mean;
        if (var < 0.f) var = 0.f;
        s_ms[threadIdx.x] = make_float2(mean, rsqrtf(var + EPS_));
    }
    __syncthreads();
}

// ---------------------------------------------------------------------------
__global__ void __launch_bounds__(THREADS, 4) spade_fused_kernel(
    const float* __restrict__ x,
    const float* __restrict__ seg,
    const float* __restrict__ wgt,
    const float* __restrict__ bia,
    float* __restrict__ out)
{
    __shared__ float2 s_wb[L_ * WB_STRIDE];   // full merged (w,b) table, 20.6 KB
    __shared__ float2 s_ms[C_];               // per-channel (mean, invstd)

    const int b = blockIdx.x;

    // Stage the full (w,b) table once.
    for (int i = threadIdx.x; i < L_ * C_; i += THREADS) {
        int l = i >> 7, c = i & (C_ - 1);
        s_wb[l * WB_STRIDE + c] = make_float2(__ldg(wgt + i), __ldg(bia + i));
    }

    // Phase 0: every block: argmax(b) ; stats(0, b)
    do_argmax_item(seg, b);
    do_stats_item(x, 0, b);
    grid_barrier();

    // Phases 1..7: every block: apply(k-1, b) ; stats(k, b) ; apply(k-1, b+512)
    for (int k = 1; k < N_; k++) {
        finalize_stats(s_ms, k - 1);
        do_apply_item(x, out, s_wb, s_ms, k - 1, b);
        do_stats_item(x, k, b);
        do_apply_item(x, out, s_wb, s_ms, k - 1, b + 512);
        grid_barrier();
    }

    // Tail: apply(7) x2
    finalize_stats(s_ms, N_ - 1);
    do_apply_item(x, out, s_wb, s_ms, N_ - 1, b);
    do_apply_item(x, out, s_wb, s_ms, N_ - 1, b + 512);
}

// ---------------------------------------------------------------------------
extern "C" void kernel_launch(void* const* d_in, const int* in_sizes, int n_in,
                              void* d_out, int out_size) {
    const float* x   = (const float*)d_in[0];
    const float* seg = (const float*)d_in[1];
    const float* wgt = (const float*)d_in[2];
    const float* bia = (const float*)d_in[3];
    float* out = (float*)d_out;

    spade_fused_kernel<<<GRID, THREADS>>>(x, seg, wgt, bia, out);
}

// round 7
// speedup vs baseline: 1.0250x; 1.0250x over previous
#include <cuda_runtime.h>

// SPADE: InstanceNorm2d(affine=False) + per-pixel class-conditional affine.
// x[8,128,256,256] f32, segmap[8,20,256,256] f32, weight/bias[20,128] f32.
//
// R7: persistent kernel, 512 co-resident blocks, phase-pipelined with
// DYNAMIC WORK STEALING inside each phase (per-phase ticket counter):
//   phase 0:   1024 tickets: {argmax(t/2), stats(0, t/2)}
//   phase k:   1536 tickets: {apply(k-1, 2u), stats(k, u), apply(k-1, 2u+1)},
//              u = t/3 — interleaved so DRAM reads + L2 reads + writes overlap
//   tail:      apply(7) static (2 items/block, no barrier after)
// Ticket counters are reset by the barrier master after all blocks arrive
// -> CUDA-graph-replay safe with zero host state. g_gen is monotonic.

#define N_   8
#define C_   128
#define H_   256
#define W_   256
#define L_   20
#define HW_  (H_ * W_)      // 65536
#define EPS_ 1e-5f

#define GRID    512
#define THREADS 256
#define CGRP    8            // channels per apply item (16 cgroups)
#define WB_STRIDE 129        // padded stride (<=2-way LDS bank conflicts)

// Quarter-plane partials (sum, sumsq), double-buffered by image parity.
__device__ float2 g_part[2][C_ * 4];
// Per-pixel argmax class id.
__device__ unsigned char g_cls[N_ * HW_];   // 512 KB
// Grid barrier + per-phase ticket counters (zero-init; reset by barrier).
__device__ unsigned int g_count = 0;
__device__ unsigned int g_gen   = 0;
__device__ unsigned int g_ticket[8] = {0, 0, 0, 0, 0, 0, 0, 0};

// ---------------------------------------------------------------------------
// Grid barrier closing phase p: master resets g_ticket[p] for the next
// launch/replay, then releases via monotonic g_gen.
// ---------------------------------------------------------------------------
__device__ __forceinline__ void grid_barrier(int p) {
    __syncthreads();
    if (threadIdx.x == 0) {
        unsigned int snap = *(volatile unsigned int*)&g_gen;
        __threadfence();                       // release this block's writes
        unsigned int t = atomicAdd(&g_count, 1u);
        if (t == GRID - 1) {
            atomicExch(&g_count, 0u);
            atomicExch(&g_ticket[p], 0u);      // all blocks arrived: safe reset
            __threadfence();
            atomicAdd(&g_gen, 1u);
        } else {
            while (*(volatile unsigned int*)&g_gen == snap) { __nanosleep(64); }
        }
        __threadfence();                       // acquire
    }
    __syncthreads();
}

// ---------------------------------------------------------------------------
// Stats item s in [0,512): plane c = s>>2, quarter q = s&3 (16384 floats).
// Normal cached loads -> x_n resident in L2 for this image's apply phase.
// ---------------------------------------------------------------------------
__device__ __forceinline__ void do_stats_item(const float* __restrict__ x, int n, int s) {
    const int c = s >> 2;
    const int q = s & 3;
    const float4* __restrict__ p =
        reinterpret_cast<const float4*>(x + (size_t)(n * C_ + c) * HW_) + q * 4096;

    float sm = 0.f, s2 = 0.f;
    #pragma unroll
    for (int i = 0; i < 16; i++) {             // 16 * 256 = 4096 float4
        float4 v = __ldg(p + i * 256 + threadIdx.x);
        sm += (v.x + v.y) + (v.z + v.w);
        s2 += v.x * v.x + v.y * v.y + v.z * v.z + v.w * v.w;
    }
    #pragma unroll
    for (int o = 16; o > 0; o >>= 1) {
        sm += __shfl_down_sync(0xFFFFFFFFu, sm, o);
        s2 += __shfl_down_sync(0xFFFFFFFFu, s2, o);
    }
    __shared__ float ss[8], ss2[8];
    const int wid = threadIdx.x >> 5, lid = threadIdx.x & 31;
    if (lid == 0) { ss[wid] = sm; ss2[wid] = s2; }
    __syncthreads();
    if (threadIdx.x == 0) {
        float ts = 0.f, ts2 = 0.f;
        #pragma unroll
        for (int i = 0; i < 8; i++) { ts += ss[i]; ts2 += ss2[i]; }
        g_part[n & 1][c * 4 + q] = make_float2(ts, ts2);
    }
    __syncthreads();
}

// ---------------------------------------------------------------------------
// Argmax item i in [0,512): 1024 consecutive pixels (thread = float4).
// ---------------------------------------------------------------------------
__device__ __forceinline__ void do_argmax_item(const float* __restrict__ seg, int i) {
    const int idx = i * THREADS + threadIdx.x;           // 0 .. 131071
    const int n   = idx >> 14;                           // / (HW/4)
    const int p4  = idx & 16383;
    const float4* __restrict__ s =
        reinterpret_cast<const float4*>(seg + (size_t)n * L_ * HW_) + p4;

    float4 best = __ldcs(s);
    int b0 = 0, b1 = 0, b2 = 0, b3 = 0;
    #pragma unroll
    for (int l = 1; l < L_; l++) {
        float4 v = __ldcs(s + (size_t)l * (HW_ / 4));
        if (v.x > best.x) { best.x = v.x; b0 = l; }
        if (v.y > best.y) { best.y = v.y; b1 = l; }
        if (v.z > best.z) { best.z = v.z; b2 = l; }
        if (v.w > best.w) { best.w = v.w; b3 = l; }
    }
    *reinterpret_cast<uchar4*>(g_cls + (size_t)n * HW_ + p4 * 4) =
        make_uchar4((unsigned char)b0, (unsigned char)b1,
                    (unsigned char)b2, (unsigned char)b3);
}

// ---------------------------------------------------------------------------
// Apply item a in [0,1024): cgroup = a&15 (8 channels), slab = a>>4 (4 rows).
// x reads: __ldcs (last use, L2 hit). out writes: __stcs (streaming).
// ---------------------------------------------------------------------------
__device__ __forceinline__ void do_apply_item(
    const float* __restrict__ x, float* __restrict__ out,
    const float2* __restrict__ s_wb, const float2* __restrict__ s_ms,
    int n, int a)
{
    const int c0  = (a & 15) * CGRP;
    const int h0  = (a >> 4) << 2;
    const int tid = threadIdx.x;

    const int r    = tid >> 6;
    const int col4 = (tid & 63) << 2;
    const int pix  = (h0 + r) * W_ + col4;

    const uchar4 cl = *reinterpret_cast<const uchar4*>(g_cls + (size_t)n * HW_ + pix);
    const int i0 = cl.x * WB_STRIDE + c0, i1 = cl.y * WB_STRIDE + c0,
              i2 = cl.z * WB_STRIDE + c0, i3 = cl.w * WB_STRIDE + c0;

    const float* __restrict__ xn = x   + (size_t)(n * C_ + c0) * HW_ + pix;
    float*       __restrict__ on = out + (size_t)(n * C_ + c0) * HW_ + pix;

    float4 v[CGRP];
    #pragma unroll
    for (int c = 0; c < CGRP; c++)
        v[c] = __ldcs(reinterpret_cast<const float4*>(xn + (size_t)c * HW_));
    #pragma unroll
    for (int c = 0; c < CGRP; c++) {
        const float2 ms = s_ms[c0 + c];
        const float2 w0 = s_wb[i0 + c];
        const float2 w1 = s_wb[i1 + c];
        const float2 w2 = s_wb[i2 + c];
        const float2 w3 = s_wb[i3 + c];
        float4 o;
        o.x = fmaf((v[c].x - ms.x) * ms.y, w0.x, w0.y);
        o.y = fmaf((v[c].y - ms.x) * ms.y, w1.x, w1.y);
        o.z = fmaf((v[c].z - ms.x) * ms.y, w2.x, w2.y);
        o.w = fmaf((v[c].w - ms.x) * ms.y, w3.x, w3.y);
        __stcs(reinterpret_cast<float4*>(on + (size_t)c * HW_), o);
    }
}

// ---------------------------------------------------------------------------
__device__ __forceinline__ void finalize_stats(float2* s_ms, int n) {
    if (threadIdx.x < C_) {
        const float2* pp = &g_part[n & 1][threadIdx.x * 4];
        float ts  = (pp[0].x + pp[1].x) + (pp[2].x + pp[3].x);
        float ts2 = (pp[0].y + pp[1].y) + (pp[2].y + pp[3].y);
        const float inv_hw = 1.0f / (float)HW_;
        float mean = ts * inv_hw;
        float var  = ts2 * inv_hw - mean * mean;
        if (var < 0.f) var = 0.f;
        s_ms[threadIdx.x] = make_float2(mean, rsqrtf(var + EPS_));
    }
    __syncthreads();
}

// ---------------------------------------------------------------------------
__global__ void __launch_bounds__(THREADS, 4) spade_fused_kernel(
    const float* __restrict__ x,
    const float* __restrict__ seg,
    const float* __restrict__ wgt,
    const float* __restrict__ bia,
    float* __restrict__ out)
{
    __shared__ float2 s_wb[L_ * WB_STRIDE];   // full merged (w,b) table
    __shared__ float2 s_ms[C_];               // per-channel (mean, invstd)
    __shared__ unsigned int s_t;              // current ticket

    // Stage the full (w,b) table once.
    for (int i = threadIdx.x; i < L_ * C_; i += THREADS) {
        int l = i >> 7, c = i & (C_ - 1);
        s_wb[l * WB_STRIDE + c] = make_float2(__ldg(wgt + i), __ldg(bia + i));
    }

    // ---- Phase 0: 1024 stolen tickets: even -> argmax, odd -> stats(0) ----
    for (;;) {
        __syncthreads();
        if (threadIdx.x == 0) s_t = atomicAdd(&g_ticket[0], 1u);
        __syncthreads();
        unsigned int t = s_t;
        if (t >= 1024u) break;
        if (t & 1u) do_stats_item(x, 0, (int)(t >> 1));
        else        do_argmax_item(seg, (int)(t >> 1));
    }
    grid_barrier(0);

    // ---- Phases 1..7: 1536 tickets each: apply/stats/apply interleaved ----
    for (int k = 1; k < N_; k++) {
        finalize_stats(s_ms, k - 1);
        for (;;) {
            __syncthreads();
            if (threadIdx.x == 0) s_t = atomicAdd(&g_ticket[k], 1u);
            __syncthreads();
            unsigned int t = s_t;
            if (t >= 1536u) break;
            unsigned int u = t / 3u, pos = t - u * 3u;
            if (pos == 1u)      do_stats_item(x, k, (int)u);
            else if (pos == 0u) do_apply_item(x, out, s_wb, s_ms, k - 1, (int)(2u * u));
            else                do_apply_item(x, out, s_wb, s_ms, k - 1, (int)(2u * u + 1u));
        }
        grid_barrier(k);
    }

    // ---- Tail: apply(7), static 2 items/block (no barrier after) ----
    finalize_stats(s_ms, N_ - 1);
    do_apply_item(x, out, s_wb, s_ms, N_ - 1, blockIdx.x);
    do_apply_item(x, out, s_wb, s_ms, N_ - 1, blockIdx.x + GRID);
}

// ---------------------------------------------------------------------------
extern "C" void kernel_launch(void* const* d_in, const int* in_sizes, int n_in,
                              void* d_out, int out_size) {
    const float* x   = (const float*)d_in[0];
    const float* seg = (const float*)d_in[1];
    const float* wgt = (const float*)d_in[2];
    const float* bia = (const float*)d_in[3];
    float* out = (float*)d_out;

    spade_fused_kernel<<<GRID, THREADS>>>(x, seg, wgt, bia, out);
}